// round 16
// baseline (speedup 1.0000x reference)
#include <cuda_runtime.h>
#include <cstdint>

#define BS    128
#define NT    25
#define MQ    1024
#define CREC  107
#define CLOC  25
#define THREADS 768
#define NWARP (THREADS / 32)
#define INFF  3.0e38f
#define PFREE 0x7fffffff
#define ARR_CAP 96

__device__ double   g_sums[BS * 2];
__device__ unsigned g_count;     // zero-init; reset by last block each launch

struct Smem {
  float  cost[NT][MQ];           // 100 KB
  unsigned long long rkey[NT];   // packed (f2ord(rowmin)<<32)|argj
  float  u[NT + 1];
  int    p[MQ + 1];
  int    way[MQ + 1];
  unsigned long long wkey[2][4]; // per-warp argmin keys, double-buffered by parity
  unsigned wkey2[2][4];          // per-warp second-min ord (ARR only)
  int    tgt_cls[NT];
  int    match_q[NT];
  int    qs_used[NT];            // greedy (speculative) query per row, -1 if pending
  float  rec_t[NT], loc_t[NT];   // per-row CE terms
  int    pend[NT + ARR_CAP + 4]; // queue (ARR appends displaced rows)
  int    npend;
  int    is64;
  int    islast;
  double red_r[4], red_l[4];
};

// focal cost via 3 MUFU (EX2, LG2, RCP). With t=e^{-x}, L=log(1+t):
//   focal = p^2 * (0.25*t^2*L - 0.75*(x+L)),  p = 1/(1+t).
__device__ __forceinline__ float focal_mufu(float x) {
  float t = __expf(-x);
  float w = 1.0f + t;
  float L = __logf(w);
  float p = __fdividef(1.0f, w);
  return p * p * (0.25f * t * t * L - 0.75f * (x + L));
}

__device__ __forceinline__ float warp_max_f(float v) {
  #pragma unroll
  for (int o = 16; o; o >>= 1) v = fmaxf(v, __shfl_xor_sync(0xffffffffu, v, o));
  return v;
}
__device__ __forceinline__ float warp_sum_f(float v) {
  #pragma unroll
  for (int o = 16; o; o >>= 1) v += __shfl_xor_sync(0xffffffffu, v, o);
  return v;
}
__device__ __forceinline__ double warp_sum_d(double v) {
  #pragma unroll
  for (int o = 16; o; o >>= 1) v += __shfl_xor_sync(0xffffffffu, v, o);
  return v;
}

// float -> order-preserving uint (finite values only)
__device__ __forceinline__ unsigned f2ord(float v) {
  unsigned u = __float_as_uint(v);
  return (u & 0x80000000u) ? ~u : (u | 0x80000000u);
}
__device__ __forceinline__ float ord2f(unsigned s) {
  unsigned u = (s & 0x80000000u) ? (s & 0x7fffffffu) : ~s;
  return __uint_as_float(u);
}

__device__ __forceinline__ void bar_wg(int id) {
  asm volatile("bar.sync %0, 128;" :: "r"(id) : "memory");
}

// CE terms for one matched (row t, query q): rec CE + loc CE, warp-collective.
__device__ __forceinline__ void ce_pair(const float* __restrict__ recb,
                                        const float* __restrict__ locb,
                                        int t, int q, int tcls, int lane,
                                        float& rec_term, float& loc_term) {
  const float* rb = recb + q;
  float v4[4];
  #pragma unroll
  for (int k = 0; k < 4; k++) {
    int c = lane + (k << 5);
    v4[k] = (c < CREC) ? __ldg(rb + (size_t)c * MQ) : -INFF;
  }
  float mx = fmaxf(fmaxf(v4[0], v4[1]), fmaxf(v4[2], v4[3]));
  mx = warp_max_f(mx);
  float se = 0.f;
  #pragma unroll
  for (int k = 0; k < 4; k++) {
    int c = lane + (k << 5);
    if (c < CREC) se += __expf(v4[k] - mx);
  }
  se = warp_sum_f(se);
  rec_term = mx + __logf(se) - __ldg(rb + (size_t)tcls * MQ);

  const float* lb = locb + q;
  float xv  = (lane < CLOC) ? __ldg(lb + (size_t)lane * MQ) : -INFF;
  float mx2 = warp_max_f(xv);
  float se2 = warp_sum_f((lane < CLOC) ? __expf(xv - mx2) : 0.f);
  loc_term = mx2 + __logf(se2) - __ldg(lb + (size_t)t * MQ);
}

__global__ __launch_bounds__(THREADS, 1)
void rec_criterion_kernel(const float* __restrict__ rec,
                          const float* __restrict__ loc,
                          const int*   __restrict__ tgt32,
                          float* __restrict__ out) {
  extern __shared__ char smem_raw[];
  Smem& S = *reinterpret_cast<Smem*>(smem_raw);
  const int b   = blockIdx.x;
  const int tid = threadIdx.x;
  const int wid = tid >> 5, lane = tid & 31;

  // ---- detection (warp 0) + init ----
  if (tid < 32) {
    int w = tgt32[2 * tid + 1];            // odd words of first 32 int64 slots
    unsigned bal = __ballot_sync(0xffffffffu, w != 0);
    if (tid == 0) S.is64 = (bal == 0u);
  }
  for (int j = tid; j <= MQ; j += THREADS) S.p[j] = PFREE;
  if (tid < NT) S.rkey[tid] = 0xFFFFFFFFFFFFFFFFull;
  __syncthreads();

  if (tid < NT) {
    int t;
    if (S.is64) t = (int)(reinterpret_cast<const long long*>(tgt32)[b * NT + tid]);
    else        t = tgt32[b * NT + tid];
    S.tgt_cls[tid] = t;
  }
  __syncthreads();

  const float* recb = rec + (size_t)b * CREC * MQ;
  const float* locb = loc + (size_t)b * CLOC * MQ;

  // ---- Phase A: quarter-row items (100) over 24 warps; float4; packed row-min ----
  for (int it = wid; it < 4 * NT; it += NWARP) {
    const int r = it >> 2, qh = it & 3;
    const float4* rp = reinterpret_cast<const float4*>(recb + (size_t)S.tgt_cls[r] * MQ);
    const float4* lp = reinterpret_cast<const float4*>(locb + (size_t)r * MQ);
    float4* crow4 = reinterpret_cast<float4*>(&S.cost[r][0]);
    float m = INFF; int jb = 0;
    float4 rv[2], lv[2];
    #pragma unroll
    for (int k = 0; k < 2; k++) rv[k] = __ldg(rp + lane + ((qh * 2 + k) << 5));
    #pragma unroll
    for (int k = 0; k < 2; k++) lv[k] = __ldg(lp + lane + ((qh * 2 + k) << 5));
    #pragma unroll
    for (int k = 0; k < 2; k++) {
      int g = lane + ((qh * 2 + k) << 5);      // float4 group; j = 4g..4g+3
      float4 c;
      c.x = fmaf(2.0f, focal_mufu(rv[k].x), focal_mufu(lv[k].x));
      c.y = fmaf(2.0f, focal_mufu(rv[k].y), focal_mufu(lv[k].y));
      c.z = fmaf(2.0f, focal_mufu(rv[k].z), focal_mufu(lv[k].z));
      c.w = fmaf(2.0f, focal_mufu(rv[k].w), focal_mufu(lv[k].w));
      crow4[g] = c;
      int j = g << 2;                           // ascending j per lane: first occurrence
      if (c.x < m) { m = c.x; jb = j; }
      if (c.y < m) { m = c.y; jb = j + 1; }
      if (c.z < m) { m = c.z; jb = j + 2; }
      if (c.w < m) { m = c.w; jb = j + 3; }
    }
    unsigned om = __reduce_min_sync(0xffffffffu, f2ord(m));
    float gm = ord2f(om);
    unsigned jc = (m == gm) ? (unsigned)jb : 0xffffffffu;
    unsigned jm = __reduce_min_sync(0xffffffffu, jc);
    if (lane == 0)
      atomicMin(&S.rkey[r], ((unsigned long long)om << 32) | (unsigned long long)jm);
  }
  __syncthreads();

  // ---- Phase B1: greedy init, parallel; also publish speculative q per row ----
  if (tid < 32) {
    bool has = tid < NT;
    int rarg = 0;
    if (has) {
      unsigned long long key = S.rkey[tid];
      rarg = (int)(key & 0xffffffffu);
      S.u[tid + 1] = ord2f((unsigned)(key >> 32));
      atomicMin(&S.p[rarg + 1], tid + 1);
    }
    if (tid == 0) S.u[0] = 0.0f;
    __syncwarp();
    bool lost = has && (S.p[rarg + 1] != tid + 1);
    unsigned mask = __ballot_sync(0xffffffffu, lost);
    if (lost) S.pend[__popc(mask & ((1u << tid) - 1u))] = tid + 1;  // ascending rows
    if (has) S.qs_used[tid] = lost ? -1 : rarg;   // speculation target (no race: pre-B2)
    if (tid == 0) S.npend = __popc(mask);
  }
  __syncthreads();

  if (wid < 4) {
    // ---- Phase B2 (4-warp workgroup, tids 0-127) ----
    // tid owns 8 contiguous cols j in [8*tid+1, 8*tid+8]; j-order == (tid,k)-order.
    const int jb0 = (tid << 3) + 1;
    float v_r[8];
    #pragma unroll
    for (int k = 0; k < 8; k++) v_r[k] = 0.0f;
    unsigned long long prow_pk = 0;
    #pragma unroll
    for (int k = 0; k < 8; k++) {
      int r = S.p[jb0 + k];
      prow_pk |= (unsigned long long)((r == PFREE) ? 255u : (unsigned)r) << (k * 8);
    }
    int head = 0, tail = S.npend;

    // ---- B2a: Augmenting Row Reduction (exact JV phase; capped) ----
    {
      int steps = 0;
      while (head < tail && steps < ARR_CAP) {
        const int i = S.pend[head];
        const float* crow = &S.cost[i - 1][0];
        // per-lane min1 (value+slot, first-occurrence) and multiplicity-exact min2
        float m1 = INFF, m2 = INFF; int bk = 0;
        #pragma unroll
        for (int k = 0; k < 8; k++) {
          float cv = crow[jb0 + k - 1] - v_r[k];
          if (cv < m1) { m2 = m1; m1 = cv; bk = k; }
          else m2 = fminf(m2, cv);
        }
        unsigned rloc = (unsigned)((prow_pk >> (bk * 8)) & 0xffu);   // 255 = free
        unsigned lowloc = ((unsigned)(jb0 + bk) << 8) |
                          ((rloc == 255u) ? 1u : (rloc << 1));
        unsigned ov1 = f2ord(m1);
        unsigned r1  = __reduce_min_sync(0xffffffffu, ov1);
        unsigned tieb = __ballot_sync(0xffffffffu, ov1 == r1);
        unsigned cand = (ov1 == r1) ? f2ord(m2) : ov1;
        unsigned m2w  = __reduce_min_sync(0xffffffffu, cand);
        if (__popc(tieb) > 1) m2w = r1;           // duplicate min value -> m2 == m1
        unsigned ll = (ov1 == r1) ? lowloc : 0xffffffffu;
        unsigned lm = __reduce_min_sync(0xffffffffu, ll);
        const int par = steps & 1;
        if (lane == 0) {
          S.wkey[par][wid]  = ((unsigned long long)r1 << 32) | (unsigned long long)lm;
          S.wkey2[par][wid] = m2w;
        }
        bar_wg(7);
        unsigned long long k0 = S.wkey[par][0], k1 = S.wkey[par][1];
        unsigned long long k2 = S.wkey[par][2], k3 = S.wkey[par][3];
        unsigned long long a = k0 < k1 ? k0 : k1, bb = k0 < k1 ? k1 : k0;
        unsigned long long c = k2 < k3 ? k2 : k3, d  = k2 < k3 ? k3 : k2;
        unsigned long long m1k = a < c ? a : c;
        unsigned long long sec = (a < c ? c : a);             // max(a,c)
        unsigned long long bd  = bb < d ? bb : d;
        unsigned long long m2k = sec < bd ? sec : bd;         // second-smallest of 4
        unsigned w0 = S.wkey2[par][0], w1 = S.wkey2[par][1];
        unsigned w2 = S.wkey2[par][2], w3 = S.wkey2[par][3];
        unsigned m2ww = min(min(w0, w1), min(w2, w3));
        unsigned u2o  = min((unsigned)(m2k >> 32), m2ww);
        float u1 = ord2f((unsigned)(m1k >> 32));
        float u2 = ord2f(u2o);
        unsigned lo = (unsigned)m1k;
        int j1    = (int)((lo >> 8) & 2047u);
        int freeb = (int)(lo & 1u);
        int rowk  = (int)((lo >> 1) & 0x3fu);
        // bookkeeping: all 128 threads write identical values (benign same-value races)
        S.u[i]  = u2;
        S.p[j1] = i;
        if (((j1 - 1) >> 3) == tid) {             // dual + cache patch by owner
          int k = (j1 - 1) & 7;
          v_r[k] -= (u2 - u1);
          prow_pk = (prow_pk & ~(0xffull << (k * 8))) |
                    ((unsigned long long)(unsigned)i << (k * 8));
        }
        head++;
        if (!freeb) { S.pend[tail] = rowk; tail++; }
        steps++;
      }
    }

    // ---- B2b: Dijkstra for remaining rows (exact fallback; usually empty) ----
    for (int pi = head; pi < tail; pi++) {
      const int i = S.pend[pi];
      float minv_r[8];
      #pragma unroll
      for (int k = 0; k < 8; k++) minv_r[k] = INFF;
      unsigned usedmask = 0u;
      float D = 0.0f;
      int j0 = 0, i0 = i, it = 0;

      while (true) {
        if (j0 > 0 && ((j0 - 1) >> 3) == tid) usedmask |= 1u << ((j0 - 1) & 7);

        const float u0p = S.u[i0] - D;
        const float4* crow4 =
            reinterpret_cast<const float4*>(&S.cost[i0 - 1][0]) + (tid << 1);

        float bv = INFF; int bk = 0;
        #pragma unroll
        for (int q = 0; q < 2; q++) {
          float4 cv = crow4[q];
          const int kq = q << 2;
          {
            int k = kq;     bool used = (usedmask >> k) & 1u;
            float cur = (cv.x - u0p) - v_r[k];
            cur = used ? INFF : cur;
            if (cur < minv_r[k]) { S.way[jb0 + k] = j0; minv_r[k] = cur; }
            float mv = used ? INFF : minv_r[k];
            if (mv < bv) { bv = mv; bk = k; }
          }
          {
            int k = kq + 1; bool used = (usedmask >> k) & 1u;
            float cur = (cv.y - u0p) - v_r[k];
            cur = used ? INFF : cur;
            if (cur < minv_r[k]) { S.way[jb0 + k] = j0; minv_r[k] = cur; }
            float mv = used ? INFF : minv_r[k];
            if (mv < bv) { bv = mv; bk = k; }
          }
          {
            int k = kq + 2; bool used = (usedmask >> k) & 1u;
            float cur = (cv.z - u0p) - v_r[k];
            cur = used ? INFF : cur;
            if (cur < minv_r[k]) { S.way[jb0 + k] = j0; minv_r[k] = cur; }
            float mv = used ? INFF : minv_r[k];
            if (mv < bv) { bv = mv; bk = k; }
          }
          {
            int k = kq + 3; bool used = (usedmask >> k) & 1u;
            float cur = (cv.w - u0p) - v_r[k];
            cur = used ? INFF : cur;
            if (cur < minv_r[k]) { S.way[jb0 + k] = j0; minv_r[k] = cur; }
            float mv = used ? INFF : minv_r[k];
            if (mv < bv) { bv = mv; bk = k; }
          }
        }
        // pack local key: low = (j<<8)|(row<<1)|free
        unsigned rloc = (unsigned)((prow_pk >> (bk * 8)) & 0xffu);   // 255 = free
        unsigned lowloc = ((unsigned)(jb0 + bk) << 8) |
                          ((rloc == 255u) ? 1u : (rloc << 1));
        unsigned ov = f2ord(bv);
        unsigned om = __reduce_min_sync(0xffffffffu, ov);
        unsigned ll = (ov == om) ? lowloc : 0xffffffffu;
        unsigned lm = __reduce_min_sync(0xffffffffu, ll);
        const int par = it & 1;
        if (lane == 0)
          S.wkey[par][wid] = ((unsigned long long)om << 32) | (unsigned long long)lm;
        bar_wg(7);
        unsigned long long k0 = S.wkey[par][0], k1 = S.wkey[par][1];
        unsigned long long k2 = S.wkey[par][2], k3 = S.wkey[par][3];
        unsigned long long km = k0 < k1 ? k0 : k1;
        if (k2 < km) km = k2;
        if (k3 < km) km = k3;
        D = ord2f((unsigned)(km >> 32));
        unsigned lo = (unsigned)km;
        j0 = (int)((lo >> 8) & 2047u);
        it++;
        if (lo & 1u) break;               // free column reached (all threads agree)
        i0 = (int)((lo >> 1) & 0x3fu);    // row assigned to j0 (from cached key)
      }

      const float Dend = D;
      // fixups: used col k entered the tree at absolute distance minv_r[k]
      unsigned mm = usedmask;
      while (mm) {
        int k = __ffs(mm) - 1; mm &= mm - 1;
        float dv = Dend - minv_r[k];
        v_r[k] -= dv;
        int r = (int)((prow_pk >> (k * 8)) & 0xffu);   // always assigned (1..25)
        S.u[r] += dv;                    // distinct rows per used col -> race-free
      }
      if (tid == 0) {
        S.u[i] += Dend;
        S.p[0] = i;
        int j = j0;                      // augment through way[]
        while (j != 0) { int jp = S.way[j]; S.p[j] = S.p[jp]; j = jp; }
      }
      bar_wg(7);                          // p visible; u visible
      // refresh cached rows (p changed along the augmenting path)
      prow_pk = 0;
      #pragma unroll
      for (int k = 0; k < 8; k++) {
        int r = S.p[jb0 + k];
        prow_pk |= (unsigned long long)((r == PFREE) ? 255u : (unsigned)r) << (k * 8);
      }
    }
    // deterministic match collection
    #pragma unroll
    for (int k = 0; k < 8; k++) {
      int r = (int)((prow_pk >> (k * 8)) & 0xffu);
      if (r != 255) S.match_q[r - 1] = jb0 + k - 1;
    }
  } else {
    // ---- Phase C (speculative): warps 4..23 compute CE for greedy-matched rows
    for (int t = wid - 4; t < NT; t += NWARP - 4) {
      int q = S.qs_used[t];
      if (q >= 0) {
        float rt, lt;
        ce_pair(recb, locb, t, q, S.tgt_cls[t], lane, rt, lt);
        if (lane == 0) { S.rec_t[t] = rt; S.loc_t[t] = lt; }
      }
    }
  }
  __syncthreads();

  // ---- Phase C fixup: recompute rows whose final q differs from speculation ----
  for (int t = wid; t < NT; t += NWARP) {
    const int q = S.match_q[t];
    if (q != S.qs_used[t]) {
      float rt, lt;
      ce_pair(recb, locb, t, q, S.tgt_cls[t], lane, rt, lt);
      if (lane == 0) { S.rec_t[t] = rt; S.loc_t[t] = lt; }
    }
  }
  __syncthreads();

  // ---- per-batch sums (warp 0, fixed deterministic order) + last-block reduce ----
  if (tid < 32) {
    double r = (lane < NT) ? (double)S.rec_t[lane] : 0.0;
    double l = (lane < NT) ? (double)S.loc_t[lane] : 0.0;
    r = warp_sum_d(r);
    l = warp_sum_d(l);
    if (lane == 0) {
      g_sums[2 * b]     = r;
      g_sums[2 * b + 1] = l;
      __threadfence();
      unsigned old = atomicAdd(&g_count, 1u);
      S.islast = (old == BS - 1);
    }
  }
  __syncthreads();

  if (S.islast) {
    double r = (tid < BS) ? g_sums[2 * tid]     : 0.0;
    double l = (tid < BS) ? g_sums[2 * tid + 1] : 0.0;
    r = warp_sum_d(r);
    l = warp_sum_d(l);
    if (lane == 0 && wid < 4) { S.red_r[wid] = r; S.red_l[wid] = l; }
    __syncthreads();
    if (tid == 0) {
      double rr = S.red_r[0] + S.red_r[1] + S.red_r[2] + S.red_r[3];
      double ll = S.red_l[0] + S.red_l[1] + S.red_l[2] + S.red_l[3];
      out[0] = (float)(rr / (double)(BS * NT));
      out[1] = (float)(ll / (double)(BS * NT));
      g_count = 0;   // reset for next replay
    }
  }
}

extern "C" void kernel_launch(void* const* d_in, const int* in_sizes, int n_in,
                              void* d_out, int out_size) {
  const float* rec = (const float*)d_in[0];
  const float* loc = (const float*)d_in[1];
  const int*   tgt = (const int*)d_in[2];
  float* out = (float*)d_out;

  const int smem = (int)sizeof(Smem);
  cudaFuncSetAttribute(rec_criterion_kernel,
                       cudaFuncAttributeMaxDynamicSharedMemorySize, smem);
  rec_criterion_kernel<<<BS, THREADS, smem>>>(rec, loc, tgt, out);
}

// round 17
// speedup vs baseline: 1.0681x; 1.0681x over previous
#include <cuda_runtime.h>
#include <cstdint>

#define BS    128
#define NT    25
#define MQ    1024
#define CREC  107
#define CLOC  25
#define THREADS 768
#define NWARP (THREADS / 32)
#define INFF  3.0e38f
#define PFREE 0x7fffffff

__device__ double   g_sums[BS * 2];
__device__ unsigned g_count;     // zero-init; reset by last block each launch

struct Smem {
  float  cost[NT][MQ];           // 100 KB
  unsigned long long rkey[NT];   // packed (f2ord(rowmin)<<32)|argj
  float  u[NT + 1];
  int    p[MQ + 1];
  int    way[MQ + 1];
  unsigned long long wkey[2][4]; // per-warp argmin keys, double-buffered by parity
  int    tgt_cls[NT];
  int    match_q[NT];
  int    qs_used[NT];            // greedy (speculative) query per row, -1 if pending
  float  rec_t[NT], loc_t[NT];   // per-row CE terms
  int    pend[NT];
  int    npend;
  int    islast;
  double red_r[4], red_l[4];
};

// focal cost via 3 MUFU (EX2, LG2, RCP). With t=e^{-x}, L=log(1+t):
//   focal = p^2 * (0.25*t^2*L - 0.75*(x+L)),  p = 1/(1+t).
__device__ __forceinline__ float focal_mufu(float x) {
  float t = __expf(-x);
  float w = 1.0f + t;
  float L = __logf(w);
  float p = __fdividef(1.0f, w);
  return p * p * (0.25f * t * t * L - 0.75f * (x + L));
}

__device__ __forceinline__ float warp_max_f(float v) {
  #pragma unroll
  for (int o = 16; o; o >>= 1) v = fmaxf(v, __shfl_xor_sync(0xffffffffu, v, o));
  return v;
}
__device__ __forceinline__ float warp_sum_f(float v) {
  #pragma unroll
  for (int o = 16; o; o >>= 1) v += __shfl_xor_sync(0xffffffffu, v, o);
  return v;
}
__device__ __forceinline__ double warp_sum_d(double v) {
  #pragma unroll
  for (int o = 16; o; o >>= 1) v += __shfl_xor_sync(0xffffffffu, v, o);
  return v;
}

// float -> order-preserving uint (finite values only)
__device__ __forceinline__ unsigned f2ord(float v) {
  unsigned u = __float_as_uint(v);
  return (u & 0x80000000u) ? ~u : (u | 0x80000000u);
}
__device__ __forceinline__ float ord2f(unsigned s) {
  unsigned u = (s & 0x80000000u) ? (s & 0x7fffffffu) : ~s;
  return __uint_as_float(u);
}

__device__ __forceinline__ void bar_wg(int id) {
  asm volatile("bar.sync %0, 128;" :: "r"(id) : "memory");
}

// CE terms for one matched (row t, query q): rec CE + loc CE, warp-collective.
__device__ __forceinline__ void ce_pair(const float* __restrict__ recb,
                                        const float* __restrict__ locb,
                                        int t, int q, int tcls, int lane,
                                        float& rec_term, float& loc_term) {
  const float* rb = recb + q;
  float v4[4];
  #pragma unroll
  for (int k = 0; k < 4; k++) {
    int c = lane + (k << 5);
    v4[k] = (c < CREC) ? __ldg(rb + (size_t)c * MQ) : -INFF;
  }
  float mx = fmaxf(fmaxf(v4[0], v4[1]), fmaxf(v4[2], v4[3]));
  mx = warp_max_f(mx);
  float se = 0.f;
  #pragma unroll
  for (int k = 0; k < 4; k++) {
    int c = lane + (k << 5);
    if (c < CREC) se += __expf(v4[k] - mx);
  }
  se = warp_sum_f(se);
  rec_term = mx + __logf(se) - __ldg(rb + (size_t)tcls * MQ);

  const float* lb = locb + q;
  float xv  = (lane < CLOC) ? __ldg(lb + (size_t)lane * MQ) : -INFF;
  float mx2 = warp_max_f(xv);
  float se2 = warp_sum_f((lane < CLOC) ? __expf(xv - mx2) : 0.f);
  loc_term = mx2 + __logf(se2) - __ldg(lb + (size_t)t * MQ);
}

__global__ __launch_bounds__(THREADS, 1)
void rec_criterion_kernel(const float* __restrict__ rec,
                          const float* __restrict__ loc,
                          const int*   __restrict__ tgt32,
                          float* __restrict__ out) {
  extern __shared__ char smem_raw[];
  Smem& S = *reinterpret_cast<Smem*>(smem_raw);
  const int b   = blockIdx.x;
  const int tid = threadIdx.x;
  const int wid = tid >> 5, lane = tid & 31;

  // ---- startup: ONE barrier. Warp 0 detects int64 via ballot and loads targets
  // immediately (is64 consumed only inside warp 0 — no smem roundtrip needed).
  if (tid < 32) {
    int w = tgt32[2 * tid + 1];            // odd words of first 32 int64 slots
    unsigned bal = __ballot_sync(0xffffffffu, w != 0);
    bool is64 = (bal == 0u);
    if (tid < NT) {
      int t;
      if (is64) t = (int)(reinterpret_cast<const long long*>(tgt32)[b * NT + tid]);
      else      t = tgt32[b * NT + tid];
      S.tgt_cls[tid] = t;
      S.rkey[tid] = 0xFFFFFFFFFFFFFFFFull;
    }
  }
  for (int j = tid; j <= MQ; j += THREADS) S.p[j] = PFREE;
  __syncthreads();

  const float* recb = rec + (size_t)b * CREC * MQ;
  const float* locb = loc + (size_t)b * CLOC * MQ;

  // ---- Phase A: quarter-row items (100) over 24 warps; float4; packed row-min ----
  for (int it = wid; it < 4 * NT; it += NWARP) {
    const int r = it >> 2, qh = it & 3;
    const float4* rp = reinterpret_cast<const float4*>(recb + (size_t)S.tgt_cls[r] * MQ);
    const float4* lp = reinterpret_cast<const float4*>(locb + (size_t)r * MQ);
    float4* crow4 = reinterpret_cast<float4*>(&S.cost[r][0]);
    float m = INFF; int jb = 0;
    float4 rv[2], lv[2];
    #pragma unroll
    for (int k = 0; k < 2; k++) rv[k] = __ldg(rp + lane + ((qh * 2 + k) << 5));
    #pragma unroll
    for (int k = 0; k < 2; k++) lv[k] = __ldg(lp + lane + ((qh * 2 + k) << 5));
    #pragma unroll
    for (int k = 0; k < 2; k++) {
      int g = lane + ((qh * 2 + k) << 5);      // float4 group; j = 4g..4g+3
      float4 c;
      c.x = fmaf(2.0f, focal_mufu(rv[k].x), focal_mufu(lv[k].x));
      c.y = fmaf(2.0f, focal_mufu(rv[k].y), focal_mufu(lv[k].y));
      c.z = fmaf(2.0f, focal_mufu(rv[k].z), focal_mufu(lv[k].z));
      c.w = fmaf(2.0f, focal_mufu(rv[k].w), focal_mufu(lv[k].w));
      crow4[g] = c;
      int j = g << 2;                           // ascending j per lane: first occurrence
      if (c.x < m) { m = c.x; jb = j; }
      if (c.y < m) { m = c.y; jb = j + 1; }
      if (c.z < m) { m = c.z; jb = j + 2; }
      if (c.w < m) { m = c.w; jb = j + 3; }
    }
    unsigned om = __reduce_min_sync(0xffffffffu, f2ord(m));
    float gm = ord2f(om);
    unsigned jc = (m == gm) ? (unsigned)jb : 0xffffffffu;
    unsigned jm = __reduce_min_sync(0xffffffffu, jc);
    if (lane == 0)
      atomicMin(&S.rkey[r], ((unsigned long long)om << 32) | (unsigned long long)jm);
  }
  __syncthreads();

  // ---- Phase B1: greedy init, parallel; also publish speculative q per row ----
  if (tid < 32) {
    bool has = tid < NT;
    int rarg = 0;
    if (has) {
      unsigned long long key = S.rkey[tid];
      rarg = (int)(key & 0xffffffffu);
      S.u[tid + 1] = ord2f((unsigned)(key >> 32));
      atomicMin(&S.p[rarg + 1], tid + 1);
    }
    if (tid == 0) S.u[0] = 0.0f;
    __syncwarp();
    bool lost = has && (S.p[rarg + 1] != tid + 1);
    unsigned mask = __ballot_sync(0xffffffffu, lost);
    if (lost) S.pend[__popc(mask & ((1u << tid) - 1u))] = tid + 1;  // ascending rows
    if (has) S.qs_used[tid] = lost ? -1 : rarg;   // speculation target (no race: pre-B2)
    if (tid == 0) S.npend = __popc(mask);
  }
  __syncthreads();

  if (wid < 4) {
    // ---- Phase B2: Dijkstra for contested rows — 4-warp workgroup, cached p ----
    // tid owns 8 contiguous cols j in [8*tid+1, 8*tid+8]; j-order == (tid,k)-order.
    const int jb0 = (tid << 3) + 1;
    float v_r[8];
    #pragma unroll
    for (int k = 0; k < 8; k++) v_r[k] = 0.0f;
    unsigned long long prow_pk = 0;
    #pragma unroll
    for (int k = 0; k < 8; k++) {
      int r = S.p[jb0 + k];
      prow_pk |= (unsigned long long)((r == PFREE) ? 255u : (unsigned)r) << (k * 8);
    }
    const int np = S.npend;

    for (int pi = 0; pi < np; pi++) {
      const int i = S.pend[pi];
      float minv_r[8];
      #pragma unroll
      for (int k = 0; k < 8; k++) minv_r[k] = INFF;
      unsigned usedmask = 0u;
      float D = 0.0f;
      int j0 = 0, i0 = i, it = 0;

      while (true) {
        if (j0 > 0 && ((j0 - 1) >> 3) == tid) usedmask |= 1u << ((j0 - 1) & 7);

        const float u0p = S.u[i0] - D;
        const float4* crow4 =
            reinterpret_cast<const float4*>(&S.cost[i0 - 1][0]) + (tid << 1);

        float bv = INFF; int bk = 0;
        #pragma unroll
        for (int q = 0; q < 2; q++) {
          float4 cv = crow4[q];
          const int kq = q << 2;
          {
            int k = kq;     bool used = (usedmask >> k) & 1u;
            float cur = (cv.x - u0p) - v_r[k];
            cur = used ? INFF : cur;
            if (cur < minv_r[k]) { S.way[jb0 + k] = j0; minv_r[k] = cur; }
            float mv = used ? INFF : minv_r[k];
            if (mv < bv) { bv = mv; bk = k; }
          }
          {
            int k = kq + 1; bool used = (usedmask >> k) & 1u;
            float cur = (cv.y - u0p) - v_r[k];
            cur = used ? INFF : cur;
            if (cur < minv_r[k]) { S.way[jb0 + k] = j0; minv_r[k] = cur; }
            float mv = used ? INFF : minv_r[k];
            if (mv < bv) { bv = mv; bk = k; }
          }
          {
            int k = kq + 2; bool used = (usedmask >> k) & 1u;
            float cur = (cv.z - u0p) - v_r[k];
            cur = used ? INFF : cur;
            if (cur < minv_r[k]) { S.way[jb0 + k] = j0; minv_r[k] = cur; }
            float mv = used ? INFF : minv_r[k];
            if (mv < bv) { bv = mv; bk = k; }
          }
          {
            int k = kq + 3; bool used = (usedmask >> k) & 1u;
            float cur = (cv.w - u0p) - v_r[k];
            cur = used ? INFF : cur;
            if (cur < minv_r[k]) { S.way[jb0 + k] = j0; minv_r[k] = cur; }
            float mv = used ? INFF : minv_r[k];
            if (mv < bv) { bv = mv; bk = k; }
          }
        }
        // pack local key: low = (j<<8)|(row<<1)|free  (row/free below j keeps (ord,j) order)
        unsigned rloc = (unsigned)((prow_pk >> (bk * 8)) & 0xffu);   // 255 = free
        unsigned lowloc = ((unsigned)(jb0 + bk) << 8) |
                          ((rloc == 255u) ? 1u : (rloc << 1));
        unsigned ov = f2ord(bv);
        unsigned om = __reduce_min_sync(0xffffffffu, ov);
        unsigned ll = (ov == om) ? lowloc : 0xffffffffu;
        unsigned lm = __reduce_min_sync(0xffffffffu, ll);
        const int par = it & 1;
        if (lane == 0)
          S.wkey[par][wid] = ((unsigned long long)om << 32) | (unsigned long long)lm;
        bar_wg(7);
        unsigned long long k0 = S.wkey[par][0], k1 = S.wkey[par][1];
        unsigned long long k2 = S.wkey[par][2], k3 = S.wkey[par][3];
        unsigned long long km = k0 < k1 ? k0 : k1;
        if (k2 < km) km = k2;
        if (k3 < km) km = k3;
        D = ord2f((unsigned)(km >> 32));
        unsigned lo = (unsigned)km;
        j0 = (int)((lo >> 8) & 2047u);
        it++;
        if (lo & 1u) break;               // free column reached (all threads agree)
        i0 = (int)((lo >> 1) & 0x3fu);    // row assigned to j0 (from cached key)
      }

      const float Dend = D;
      // fixups: used col k entered the tree at absolute distance minv_r[k]
      unsigned mm = usedmask;
      while (mm) {
        int k = __ffs(mm) - 1; mm &= mm - 1;
        float dv = Dend - minv_r[k];
        v_r[k] -= dv;
        int r = (int)((prow_pk >> (k * 8)) & 0xffu);   // always assigned (1..25)
        S.u[r] += dv;                    // distinct rows per used col -> race-free
      }
      if (tid == 0) {
        S.u[i] += Dend;
        S.p[0] = i;
        int j = j0;                      // augment through way[]
        while (j != 0) { int jp = S.way[j]; S.p[j] = S.p[jp]; j = jp; }
      }
      bar_wg(7);                          // p visible; u visible
      // refresh cached rows (p changed along the augmenting path)
      prow_pk = 0;
      #pragma unroll
      for (int k = 0; k < 8; k++) {
        int r = S.p[jb0 + k];
        prow_pk |= (unsigned long long)((r == PFREE) ? 255u : (unsigned)r) << (k * 8);
      }
    }
    // deterministic match collection
    #pragma unroll
    for (int k = 0; k < 8; k++) {
      int r = S.p[jb0 + k];
      if (r != PFREE && r > 0) S.match_q[r - 1] = jb0 + k - 1;
    }
  } else {
    // ---- Phase C (speculative): warps 4..23 compute CE for greedy-matched rows
    // concurrently with B2. Reads: qs_used/tgt_cls (stable), global rec/loc.
    for (int t = wid - 4; t < NT; t += NWARP - 4) {
      int q = S.qs_used[t];
      if (q >= 0) {
        float rt, lt;
        ce_pair(recb, locb, t, q, S.tgt_cls[t], lane, rt, lt);
        if (lane == 0) { S.rec_t[t] = rt; S.loc_t[t] = lt; }
      }
    }
  }
  __syncthreads();

  // ---- Phase C fixup: recompute rows whose final q differs from speculation ----
  for (int t = wid; t < NT; t += NWARP) {
    const int q = S.match_q[t];
    if (q != S.qs_used[t]) {
      float rt, lt;
      ce_pair(recb, locb, t, q, S.tgt_cls[t], lane, rt, lt);
      if (lane == 0) { S.rec_t[t] = rt; S.loc_t[t] = lt; }
    }
  }
  __syncthreads();

  // ---- per-batch sums (warp 0, fixed deterministic order) + last-block reduce ----
  if (tid < 32) {
    double r = (lane < NT) ? (double)S.rec_t[lane] : 0.0;
    double l = (lane < NT) ? (double)S.loc_t[lane] : 0.0;
    r = warp_sum_d(r);
    l = warp_sum_d(l);
    if (lane == 0) {
      g_sums[2 * b]     = r;
      g_sums[2 * b + 1] = l;
      __threadfence();
      unsigned old = atomicAdd(&g_count, 1u);
      S.islast = (old == BS - 1);
    }
  }
  __syncthreads();

  if (S.islast) {
    double r = (tid < BS) ? g_sums[2 * tid]     : 0.0;
    double l = (tid < BS) ? g_sums[2 * tid + 1] : 0.0;
    r = warp_sum_d(r);
    l = warp_sum_d(l);
    if (lane == 0 && wid < 4) { S.red_r[wid] = r; S.red_l[wid] = l; }
    __syncthreads();
    if (tid == 0) {
      double rr = S.red_r[0] + S.red_r[1] + S.red_r[2] + S.red_r[3];
      double ll = S.red_l[0] + S.red_l[1] + S.red_l[2] + S.red_l[3];
      out[0] = (float)(rr / (double)(BS * NT));
      out[1] = (float)(ll / (double)(BS * NT));
      g_count = 0;   // reset for next replay
    }
  }
}

extern "C" void kernel_launch(void* const* d_in, const int* in_sizes, int n_in,
                              void* d_out, int out_size) {
  const float* rec = (const float*)d_in[0];
  const float* loc = (const float*)d_in[1];
  const int*   tgt = (const int*)d_in[2];
  float* out = (float*)d_out;

  const int smem = (int)sizeof(Smem);
  cudaFuncSetAttribute(rec_criterion_kernel,
                       cudaFuncAttributeMaxDynamicSharedMemorySize, smem);
  rec_criterion_kernel<<<BS, THREADS, smem>>>(rec, loc, tgt, out);
}